// round 1
// baseline (speedup 1.0000x reference)
#include <cuda_runtime.h>
#include <math.h>

// Problem constants
#define BQ   4
#define LQ   60
#define HQ   768
#define IQ   1536
#define NQ   16
#define RQ   48
#define NLYR 32
#define BL   240      // B*L rows
#define SPW  80       // R + 2N

// ---------------- device scratch (allocation-free) ----------------
__device__ float g_h  [BL * HQ];        // residual stream
__device__ float g_io [BL * 2 * IQ];    // in-proj output: [0:1536]=hs_raw, [1536:3072]=gate
__device__ float g_hs2[BL * IQ];        // conv+silu output
__device__ float g_dt [BL * IQ];        // softplus(dt)
__device__ float g_sp [BL * SPW];       // x-proj output (dt_in | B | C)
__device__ float g_yc [BL * IQ];        // combined y (input to out-proj GEMM)
__device__ float g_hf [BL * HQ];        // final rmsnorm output
__device__ float g_sc [BL * 4];         // attention logits
__device__ float g_m  [BQ * 4 * HQ];    // pooled, flattened

// ---------------- input MLP: x(240,13) -> h(240,768) ----------------
__global__ void k_in_mlp(const float* __restrict__ x,
                         const float* __restrict__ iw1, const float* __restrict__ ib1,
                         const float* __restrict__ iw2, const float* __restrict__ ib2,
                         const float* __restrict__ iw3, const float* __restrict__ ib3) {
    int r = blockIdx.x, tid = threadIdx.x;
    __shared__ float xr[13];
    __shared__ float h1[256];
    __shared__ float h2[256];
    if (tid < 13) xr[tid] = x[r * 13 + tid];
    __syncthreads();
    float a = ib1[tid];
#pragma unroll
    for (int k = 0; k < 13; k++) a += xr[k] * iw1[k * 256 + tid];
    h1[tid] = fmaxf(a, 0.f);
    __syncthreads();
    a = ib2[tid];
    for (int k = 0; k < 256; k++) a += h1[k] * iw2[k * 256 + tid];
    h2[tid] = fmaxf(a, 0.f);
    __syncthreads();
#pragma unroll
    for (int ii = 0; ii < 3; ii++) {
        int c = tid + ii * 256;
        float v = ib3[c];
        for (int k = 0; k < 256; k++) v += h2[k] * iw3[k * 768 + c];
        g_h[r * 768 + c] = v;
    }
}

// ---------------- in-proj GEMM with fused rmsnorm ----------------
// grid (24, 15): 128-col x 16-row tiles. C(240,3072) = rmsnorm(h)*norm_w @ in_w[l]
__global__ void k_gemm_in(const float* __restrict__ in_w,
                          const float* __restrict__ norm_w, int l) {
    int col0 = blockIdx.x * 128, row0 = blockIdx.y * 16;
    int tid = threadIdx.x;
    __shared__ float rstd[16];
    __shared__ float As[16][64];
    __shared__ float4 Ws[64][32];

    int lane = tid & 31, w = tid >> 5;
    // per-row inv-rms (warp w handles rows w, w+8)
    for (int rr = w; rr < 16; rr += 8) {
        float ss = 0.f;
        const float* hr = &g_h[(row0 + rr) * 768];
        for (int k = lane; k < 768; k += 32) { float v = hr[k]; ss += v * v; }
#pragma unroll
        for (int o = 16; o > 0; o >>= 1) ss += __shfl_xor_sync(0xffffffffu, ss, o);
        if (lane == 0) rstd[rr] = rsqrtf(ss * (1.f / 768.f) + 1e-5f);
    }
    __syncthreads();

    const float* W  = in_w + (size_t)l * 768 * 3072;
    const float* nw = norm_w + l * 768;
    int ty = tid >> 4, tx = tid & 15;
    float acc[8] = {0, 0, 0, 0, 0, 0, 0, 0};

    for (int k0 = 0; k0 < 768; k0 += 64) {
#pragma unroll
        for (int it = 0; it < 4; it++) {
            int e = tid + it * 256;
            int rr = e >> 6, cc = e & 63;
            As[rr][cc] = g_h[(row0 + rr) * 768 + k0 + cc] * rstd[rr] * nw[k0 + cc];
        }
#pragma unroll
        for (int it = 0; it < 8; it++) {
            int e = tid + it * 256;
            int kk = e >> 5, c4 = e & 31;
            Ws[kk][c4] = *(const float4*)&W[(size_t)(k0 + kk) * 3072 + col0 + c4 * 4];
        }
        __syncthreads();
#pragma unroll
        for (int kk = 0; kk < 64; kk++) {
            float a = As[ty][kk];
            float4 w0 = Ws[kk][2 * tx];
            float4 w1 = Ws[kk][2 * tx + 1];
            acc[0] += a * w0.x; acc[1] += a * w0.y; acc[2] += a * w0.z; acc[3] += a * w0.w;
            acc[4] += a * w1.x; acc[5] += a * w1.y; acc[6] += a * w1.z; acc[7] += a * w1.w;
        }
        __syncthreads();
    }
    float* o = &g_io[(size_t)(row0 + ty) * 3072 + col0 + tx * 8];
#pragma unroll
    for (int j = 0; j < 8; j++) o[j] = acc[j];
}

// ---------------- conv + silu + x-proj + dt-proj + softplus ----------------
// one block per (b,t) row
__global__ void k_xproj(const float* __restrict__ conv_w, const float* __restrict__ conv_b,
                        const float* __restrict__ xp_w,
                        const float* __restrict__ dt_w, const float* __restrict__ dt_b, int l) {
    int r = blockIdx.x;
    int t = r % 60;
    int tid = threadIdx.x;
    __shared__ float hs2s[1536];
    __shared__ float part[240];
    __shared__ float sps[80];

    const float4* cw4 = (const float4*)(conv_w + (size_t)l * 1536 * 4);
    const float*  cb  = conv_b + l * 1536;

    // depthwise causal conv (K=4) + silu
#pragma unroll
    for (int ii = 0; ii < 6; ii++) {
        int i = tid + ii * 256;
        float4 w = cw4[i];                     // w.x=conv_w[i][0] .. w.w=conv_w[i][3]
        float acc = cb[i];
        const float* hsc = &g_io[(size_t)r * 3072 + i];
        acc += hsc[0] * w.w;                   // hs[t]   * w[3]
        if (t >= 1) acc += hsc[-3072]     * w.z;
        if (t >= 2) acc += hsc[-2 * 3072] * w.y;
        if (t >= 3) acc += hsc[-3 * 3072] * w.x;
        float v = acc / (1.f + __expf(-acc));  // silu
        hs2s[i] = v;
        g_hs2[(size_t)r * 1536 + i] = v;
    }
    __syncthreads();

    // sp = hs2 @ xp_w[l]  (80 outputs, K=1536) via 3-way split-K
    if (tid < 240) {
        int o = tid % 80, p = tid / 80;
        const float* Wx = xp_w + (size_t)l * 1536 * 80;
        float s = 0.f;
        int k0 = p * 512;
        for (int k = k0; k < k0 + 512; k++) s += hs2s[k] * Wx[k * 80 + o];
        part[tid] = s;
    }
    __syncthreads();
    if (tid < 80) {
        float v = part[tid] + part[tid + 80] + part[tid + 160];
        sps[tid] = v;
        g_sp[r * 80 + tid] = v;
    }
    __syncthreads();

    // dt = softplus(sp[:48] @ dt_w[l] + dt_b[l])
    const float* Wd = dt_w + (size_t)l * 48 * 1536;
    const float* db = dt_b + l * 1536;
#pragma unroll
    for (int ii = 0; ii < 6; ii++) {
        int i = tid + ii * 256;
        float d = db[i];
#pragma unroll
        for (int rr = 0; rr < 48; rr++) d += sps[rr] * Wd[rr * 1536 + i];
        d = (d > 15.f) ? d : log1pf(__expf(d));
        g_dt[r * 1536 + i] = d;
    }
}

// ---------------- selective scan (fused dA exp, C-reduce, gate/Dp combine) ----
// thread = (b, i, n): 384 blocks x 256 threads; 16 lanes per (b,i) chain
__global__ void k_scan(const float* __restrict__ A_log, const float* __restrict__ Dp, int l) {
    int b = blockIdx.x / 96;
    int itile = blockIdx.x % 96;
    int tid = threadIdx.x;
    int n = tid & 15, ci = tid >> 4;
    int i = itile * 16 + ci;

    float A  = -expf(A_log[((size_t)l * 1536 + i) * 16 + n]);
    float Dv = Dp[l * 1536 + i];
    float state = 0.f;

    for (int t = 0; t < 60; t++) {
        int r = b * 60 + t;
        float dtv = g_dt[r * 1536 + i];
        float hsv = g_hs2[r * 1536 + i];
        float Bv  = g_sp[r * 80 + 48 + n];
        float Cv  = g_sp[r * 80 + 64 + n];
        float dA  = __expf(dtv * A);
        state = fmaf(dA, state, dtv * hsv * Bv);
        float p = state * Cv;
        p += __shfl_xor_sync(0xffffffffu, p, 8);
        p += __shfl_xor_sync(0xffffffffu, p, 4);
        p += __shfl_xor_sync(0xffffffffu, p, 2);
        p += __shfl_xor_sync(0xffffffffu, p, 1);
        if (n == 0) {
            float gv = g_io[(size_t)r * 3072 + 1536 + i];
            float sg = gv / (1.f + __expf(-gv));      // silu(gate)
            g_yc[r * 1536 + i] = (p + hsv * Dv) * sg;
        }
    }
}

// ---------------- out-proj GEMM with residual add ----------------
// grid (6, 15). g_h += g_yc(240,1536) @ out_w[l](1536,768)
__global__ void k_gemm_out(const float* __restrict__ out_w, int l) {
    int col0 = blockIdx.x * 128, row0 = blockIdx.y * 16;
    int tid = threadIdx.x;
    __shared__ float As[16][64];
    __shared__ float4 Ws[64][32];

    const float* W = out_w + (size_t)l * 1536 * 768;
    int ty = tid >> 4, tx = tid & 15;
    float acc[8] = {0, 0, 0, 0, 0, 0, 0, 0};

    for (int k0 = 0; k0 < 1536; k0 += 64) {
#pragma unroll
        for (int it = 0; it < 4; it++) {
            int e = tid + it * 256;
            int rr = e >> 6, cc = e & 63;
            As[rr][cc] = g_yc[(size_t)(row0 + rr) * 1536 + k0 + cc];
        }
#pragma unroll
        for (int it = 0; it < 8; it++) {
            int e = tid + it * 256;
            int kk = e >> 5, c4 = e & 31;
            Ws[kk][c4] = *(const float4*)&W[(size_t)(k0 + kk) * 768 + col0 + c4 * 4];
        }
        __syncthreads();
#pragma unroll
        for (int kk = 0; kk < 64; kk++) {
            float a = As[ty][kk];
            float4 w0 = Ws[kk][2 * tx];
            float4 w1 = Ws[kk][2 * tx + 1];
            acc[0] += a * w0.x; acc[1] += a * w0.y; acc[2] += a * w0.z; acc[3] += a * w0.w;
            acc[4] += a * w1.x; acc[5] += a * w1.y; acc[6] += a * w1.z; acc[7] += a * w1.w;
        }
        __syncthreads();
    }
    float* o = &g_h[(size_t)(row0 + ty) * 768 + col0 + tx * 8];
#pragma unroll
    for (int j = 0; j < 8; j++) o[j] += acc[j];
}

// ---------------- final rmsnorm + attention logits ----------------
__global__ void k_final(const float* __restrict__ fnorm_w,
                        const float* __restrict__ ws1, const float* __restrict__ ws2) {
    int r = blockIdx.x, tid = threadIdx.x;
    __shared__ float hf[768];
    __shared__ float al[128];
    __shared__ float red[256];
    float ss = 0.f;
    for (int k = tid; k < 768; k += 256) { float v = g_h[r * 768 + k]; ss += v * v; }
    red[tid] = ss;
    __syncthreads();
    for (int s = 128; s > 0; s >>= 1) { if (tid < s) red[tid] += red[tid + s]; __syncthreads(); }
    float rstd = rsqrtf(red[0] * (1.f / 768.f) + 1e-5f);
#pragma unroll
    for (int ii = 0; ii < 3; ii++) {
        int c = tid + ii * 256;
        float v = g_h[r * 768 + c] * rstd * fnorm_w[c];
        hf[c] = v;
        g_hf[r * 768 + c] = v;
    }
    __syncthreads();
    if (tid < 128) {
        float a = 0.f;
        for (int k = 0; k < 768; k++) a += hf[k] * ws1[k * 128 + tid];
        al[tid] = tanhf(a);
    }
    __syncthreads();
    if (tid < 4) {
        float s = 0.f;
        for (int d = 0; d < 128; d++) s += al[d] * ws2[d * 4 + tid];
        g_sc[r * 4 + tid] = s;
    }
}

// ---------------- softmax(axis=L) + pooling ----------------
__global__ void k_pool() {
    int b = blockIdx.x >> 2, rr = blockIdx.x & 3;
    int tid = threadIdx.x;
    __shared__ float att[60];
    __shared__ float mx_s, inv_s;
    if (tid < 60) att[tid] = g_sc[(b * 60 + tid) * 4 + rr];
    __syncthreads();
    if (tid == 0) {
        float m = -1e30f;
        for (int t = 0; t < 60; t++) m = fmaxf(m, att[t]);
        mx_s = m;
    }
    __syncthreads();
    if (tid < 60) att[tid] = __expf(att[tid] - mx_s);
    __syncthreads();
    if (tid == 0) {
        float s = 0.f;
        for (int t = 0; t < 60; t++) s += att[t];
        inv_s = 1.f / s;
    }
    __syncthreads();
    for (int c = tid; c < 768; c += 256) {
        float acc = 0.f;
        for (int t = 0; t < 60; t++) acc += att[t] * g_hf[(b * 60 + t) * 768 + c];
        g_m[b * 3072 + rr * 768 + c] = acc * inv_s;
    }
}

// ---------------- output MLP ----------------
__global__ void k_out_mlp(const float* __restrict__ ow1, const float* __restrict__ ob1,
                          const float* __restrict__ ow2, const float* __restrict__ ob2,
                          const float* __restrict__ ow3, const float* __restrict__ ob3,
                          float* __restrict__ out) {
    int b = blockIdx.x, tid = threadIdx.x;
    __shared__ float o1[256];
    __shared__ float o2[256];
    __shared__ float red[256];
    float a = ob1[tid];
    for (int k = 0; k < 3072; k++) a += g_m[b * 3072 + k] * ow1[k * 256 + tid];
    o1[tid] = fmaxf(a, 0.f);
    __syncthreads();
    a = ob2[tid];
    for (int k = 0; k < 256; k++) a += o1[k] * ow2[k * 256 + tid];
    o2[tid] = fmaxf(a, 0.f);
    __syncthreads();
    red[tid] = o2[tid] * ow3[tid];
    __syncthreads();
    for (int s = 128; s > 0; s >>= 1) { if (tid < s) red[tid] += red[tid + s]; __syncthreads(); }
    if (tid == 0) out[b] = red[0] + ob3[0];
}

// ---------------- launch ----------------
extern "C" void kernel_launch(void* const* d_in, const int* in_sizes, int n_in,
                              void* d_out, int out_size) {
    const float* x      = (const float*)d_in[0];
    const float* iw1    = (const float*)d_in[1];
    const float* ib1    = (const float*)d_in[2];
    const float* iw2    = (const float*)d_in[3];
    const float* ib2    = (const float*)d_in[4];
    const float* iw3    = (const float*)d_in[5];
    const float* ib3    = (const float*)d_in[6];
    const float* norm_w = (const float*)d_in[7];
    const float* in_w   = (const float*)d_in[8];
    const float* conv_w = (const float*)d_in[9];
    const float* conv_b = (const float*)d_in[10];
    const float* xp_w   = (const float*)d_in[11];
    const float* dt_w   = (const float*)d_in[12];
    const float* dt_b   = (const float*)d_in[13];
    const float* A_log  = (const float*)d_in[14];
    const float* Dp     = (const float*)d_in[15];
    const float* out_w  = (const float*)d_in[16];
    const float* fnorm_w= (const float*)d_in[17];
    const float* ws1    = (const float*)d_in[18];
    const float* ws2    = (const float*)d_in[19];
    const float* ow1    = (const float*)d_in[20];
    const float* ob1    = (const float*)d_in[21];
    const float* ow2    = (const float*)d_in[22];
    const float* ob2    = (const float*)d_in[23];
    const float* ow3    = (const float*)d_in[24];
    const float* ob3    = (const float*)d_in[25];

    k_in_mlp<<<BL, 256>>>(x, iw1, ib1, iw2, ib2, iw3, ib3);
    for (int l = 0; l < NLYR; l++) {
        k_gemm_in<<<dim3(24, 15), 256>>>(in_w, norm_w, l);
        k_xproj<<<BL, 256>>>(conv_w, conv_b, xp_w, dt_w, dt_b, l);
        k_scan<<<384, 256>>>(A_log, Dp, l);
        k_gemm_out<<<dim3(6, 15), 256>>>(out_w, l);
    }
    k_final<<<BL, 256>>>(fnorm_w, ws1, ws2);
    k_pool<<<16, 256>>>();
    k_out_mlp<<<4, 256>>>(ow1, ob1, ow2, ob2, ow3, ob3, (float*)d_out);
}

// round 2
// speedup vs baseline: 2.4046x; 2.4046x over previous
#include <cuda_runtime.h>
#include <math.h>

#define BQ   4
#define LQ   60
#define HQ   768
#define IQ   1536
#define NQ   16
#define RQ   48
#define NLYR 32
#define BL   240

// ---------------- device scratch ----------------
__device__ float g_h  [BL * HQ];
__device__ float g_an [BL * HQ];        // rmsnorm output (GEMM A)
__device__ float g_io [BL * 2 * IQ];    // in-proj out: hs | gate
__device__ float g_hs2[BL * IQ];        // conv+silu
__device__ float g_dt [BL * IQ];
__device__ float g_sp [BL * 80];
__device__ float g_yc [BL * IQ];
__device__ float g_hf [BL * HQ];
__device__ float g_sc [BL * 4];
__device__ float g_m  [BQ * 4 * HQ];

__device__ __forceinline__ unsigned su32(const void* p) {
    unsigned a;
    asm("{ .reg .u64 t; cvta.to.shared.u64 t, %1; cvt.u32.u64 %0, t; }" : "=r"(a) : "l"(p));
    return a;
}
#define CPA16(dst, src) asm volatile("cp.async.cg.shared.global [%0], [%1], 16;" :: "r"(dst), "l"(src))
#define CPCOMMIT()      asm volatile("cp.async.commit_group;")
#define CPWAIT1()       asm volatile("cp.async.wait_group 1;")

// ---------------- input MLP ----------------
__global__ void k_in_mlp(const float* __restrict__ x,
                         const float* __restrict__ iw1, const float* __restrict__ ib1,
                         const float* __restrict__ iw2, const float* __restrict__ ib2,
                         const float* __restrict__ iw3, const float* __restrict__ ib3) {
    int r = blockIdx.x, tid = threadIdx.x;
    __shared__ float xr[13];
    __shared__ float h1[256];
    __shared__ float h2[256];
    if (tid < 13) xr[tid] = x[r * 13 + tid];
    __syncthreads();
    float a = ib1[tid];
#pragma unroll
    for (int k = 0; k < 13; k++) a += xr[k] * iw1[k * 256 + tid];
    h1[tid] = fmaxf(a, 0.f);
    __syncthreads();
    a = ib2[tid];
    for (int k = 0; k < 256; k++) a += h1[k] * iw2[k * 256 + tid];
    h2[tid] = fmaxf(a, 0.f);
    __syncthreads();
#pragma unroll
    for (int ii = 0; ii < 3; ii++) {
        int c = tid + ii * 256;
        float v = ib3[c];
        for (int k = 0; k < 256; k++) v += h2[k] * iw3[k * 768 + c];
        g_h[r * 768 + c] = v;
    }
}

// ---------------- rmsnorm: g_an = rmsnorm(g_h) * norm_w[l] ----------------
__global__ void k_norm(const float* __restrict__ norm_w, int l) {
    int r = blockIdx.x, tid = threadIdx.x;
    __shared__ float red[8];
    float v0 = g_h[r * 768 + tid];
    float v1 = g_h[r * 768 + 256 + tid];
    float v2 = g_h[r * 768 + 512 + tid];
    float ss = v0 * v0 + v1 * v1 + v2 * v2;
#pragma unroll
    for (int o = 16; o > 0; o >>= 1) ss += __shfl_xor_sync(0xffffffffu, ss, o);
    if ((tid & 31) == 0) red[tid >> 5] = ss;
    __syncthreads();
    float tot = red[0] + red[1] + red[2] + red[3] + red[4] + red[5] + red[6] + red[7];
    float rstd = rsqrtf(tot * (1.f / 768.f) + 1e-5f);
    const float* nw = norm_w + l * 768;
    g_an[r * 768 + tid]       = v0 * rstd * nw[tid];
    g_an[r * 768 + 256 + tid] = v1 * rstd * nw[256 + tid];
    g_an[r * 768 + 512 + tid] = v2 * rstd * nw[512 + tid];
}

// ---------------- in-proj GEMM: g_io(240,3072) = g_an(240,768) @ in_w[l] ----
// grid (24,15), 256 thr; tile 16x128, thread 2x4, cp.async double-buffered
__global__ void __launch_bounds__(256, 1) k_gemm_in(const float* __restrict__ in_w, int l) {
    __shared__ float As[2][16][32];
    __shared__ float Ws[2][32][128];
    const float* W = in_w + (size_t)l * 768 * 3072;
    int tid = threadIdx.x;
    int col0 = blockIdx.x * 128, row0 = blockIdx.y * 16;
    unsigned aA = su32(As), aW = su32(Ws);
    int arr = tid >> 3, af = (tid & 7) * 4;
    const float* asrc = &g_an[(size_t)(row0 + arr) * 768 + af];

#define ISSUE_IN(s, k0) do { \
    if (tid < 128) CPA16(aA + (unsigned)(((s) * 512 + arr * 32 + af) * 4), asrc + (k0)); \
    _Pragma("unroll") \
    for (int p = 0; p < 4; p++) { int e = tid + p * 256; int kk = e >> 5, cc = (e & 31) * 4; \
        CPA16(aW + (unsigned)(((s) * 4096 + kk * 128 + cc) * 4), &W[(size_t)((k0) + kk) * 3072 + col0 + cc]); } \
    CPCOMMIT(); } while (0)

    ISSUE_IN(0, 0);
    int ty = tid >> 5, txx = tid & 31;
    float acc[8] = {0, 0, 0, 0, 0, 0, 0, 0};
#pragma unroll 1
    for (int kt = 0; kt < 24; kt++) {
        __syncthreads();
        if (kt < 23) ISSUE_IN((kt + 1) & 1, (kt + 1) * 32); else CPCOMMIT();
        CPWAIT1();
        __syncthreads();
        int s = kt & 1;
#pragma unroll
        for (int kk = 0; kk < 32; kk++) {
            float a0 = As[s][ty][kk], a1 = As[s][ty + 8][kk];
            float4 b = *(const float4*)&Ws[s][kk][txx * 4];
            acc[0] = fmaf(a0, b.x, acc[0]); acc[1] = fmaf(a0, b.y, acc[1]);
            acc[2] = fmaf(a0, b.z, acc[2]); acc[3] = fmaf(a0, b.w, acc[3]);
            acc[4] = fmaf(a1, b.x, acc[4]); acc[5] = fmaf(a1, b.y, acc[5]);
            acc[6] = fmaf(a1, b.z, acc[6]); acc[7] = fmaf(a1, b.w, acc[7]);
        }
    }
    size_t o0 = (size_t)(row0 + ty) * 3072 + col0 + txx * 4;
    *(float4*)&g_io[o0]             = make_float4(acc[0], acc[1], acc[2], acc[3]);
    *(float4*)&g_io[o0 + 8 * 3072]  = make_float4(acc[4], acc[5], acc[6], acc[7]);
#undef ISSUE_IN
}

// ---------------- conv+silu fused with sp-projection (4 rows/block) --------
__global__ void __launch_bounds__(256) k_sp(const float* __restrict__ conv_w,
                                            const float* __restrict__ conv_b,
                                            const float* __restrict__ xp_w, int l) {
    __shared__ float hs2s[4][1536];
    __shared__ float part[3][4][80];
    int tid = threadIdx.x;
    int r0 = blockIdx.x * 4;
    const float4* cw4 = (const float4*)(conv_w + (size_t)l * 1536 * 4);
    const float*  cb  = conv_b + l * 1536;
#pragma unroll
    for (int rr = 0; rr < 4; rr++) {
        int r = r0 + rr, t = r % 60;
#pragma unroll
        for (int ii = 0; ii < 6; ii++) {
            int i = tid + ii * 256;
            float4 w = cw4[i];
            const float* hsc = &g_io[(size_t)r * 3072 + i];
            float a = cb[i] + hsc[0] * w.w;
            if (t >= 1) a += hsc[-3072] * w.z;
            if (t >= 2) a += hsc[-6144] * w.y;
            if (t >= 3) a += hsc[-9216] * w.x;
            float v = a / (1.f + __expf(-a));
            hs2s[rr][i] = v;
            g_hs2[(size_t)r * 1536 + i] = v;
        }
    }
    __syncthreads();
    if (tid < 240) {
        int o = tid % 80, ks = tid / 80;
        const float* Wx = xp_w + (size_t)l * 1536 * 80;
        float a0 = 0, a1 = 0, a2 = 0, a3 = 0;
        int k0 = ks * 512;
        for (int k = k0; k < k0 + 512; k++) {
            float w = Wx[k * 80 + o];
            a0 = fmaf(hs2s[0][k], w, a0);
            a1 = fmaf(hs2s[1][k], w, a1);
            a2 = fmaf(hs2s[2][k], w, a2);
            a3 = fmaf(hs2s[3][k], w, a3);
        }
        part[ks][0][o] = a0; part[ks][1][o] = a1; part[ks][2][o] = a2; part[ks][3][o] = a3;
    }
    __syncthreads();
    if (tid < 80) {
#pragma unroll
        for (int rr = 0; rr < 4; rr++)
            g_sp[(r0 + rr) * 80 + tid] = part[0][rr][tid] + part[1][rr][tid] + part[2][rr][tid];
    }
}

// ---------------- dt = softplus(sp[:,:48] @ dt_w + dt_b), 8 rows/block ------
__global__ void __launch_bounds__(256) k_dt(const float* __restrict__ dt_w,
                                            const float* __restrict__ dt_b, int l) {
    __shared__ float sps[8][48];
    int tid = threadIdx.x;
    int r0 = blockIdx.y * 8;
    int c = blockIdx.x * 256 + tid;
    for (int e = tid; e < 384; e += 256)
        sps[e / 48][e % 48] = g_sp[(r0 + e / 48) * 80 + (e % 48)];
    __syncthreads();
    const float* Wd = dt_w + (size_t)l * 48 * 1536;
    float bias = dt_b[l * 1536 + c];
    float acc[8];
#pragma unroll
    for (int rr = 0; rr < 8; rr++) acc[rr] = bias;
#pragma unroll 4
    for (int k = 0; k < 48; k++) {
        float w = Wd[k * 1536 + c];
#pragma unroll
        for (int rr = 0; rr < 8; rr++) acc[rr] = fmaf(sps[rr][k], w, acc[rr]);
    }
#pragma unroll
    for (int rr = 0; rr < 8; rr++) {
        float d = acc[rr];
        d = (d > 15.f) ? d : log1pf(__expf(d));
        g_dt[(size_t)(r0 + rr) * 1536 + c] = d;
    }
}

// ---------------- selective scan: staged smem, 8 states/thread --------------
// grid 192 (4b x 48 i-tiles of 32), 64 threads; thread = (i, n-half)
__global__ void __launch_bounds__(64) k_scan(const float* __restrict__ A_log,
                                             const float* __restrict__ Dp, int l) {
    __shared__ float sdt[60][32];
    __shared__ float shs[60][32];
    __shared__ float sbc[60][32];
    __shared__ float sgt[60][32];
    int tid = threadIdx.x;
    int b = blockIdx.x / 48, ic = blockIdx.x % 48, i0 = ic * 32;
    int p = tid >> 1, nh = tid & 1;
    int i = i0 + p;

    for (int e = tid; e < 1920; e += 64) {
        int t = e >> 5, j = e & 31;
        int r = b * 60 + t;
        sdt[t][j] = g_dt [(size_t)r * 1536 + i0 + j];
        shs[t][j] = g_hs2[(size_t)r * 1536 + i0 + j];
        sbc[t][j] = g_sp [r * 80 + 48 + j];
        sgt[t][j] = g_io [(size_t)r * 3072 + 1536 + i0 + j];
    }
    float A[8], st[8];
    const float* Ap = &A_log[((size_t)l * 1536 + i) * 16 + nh * 8];
#pragma unroll
    for (int j = 0; j < 8; j++) { A[j] = -__expf(Ap[j]); st[j] = 0.f; }
    float Dv = Dp[l * 1536 + i];
    __syncthreads();

    for (int t = 0; t < 60; t++) {
        float dtv = sdt[t][p], hsv = shs[t][p];
        float du = dtv * hsv;
        float ys = 0.f;
#pragma unroll
        for (int j = 0; j < 8; j++) {
            float dA = __expf(dtv * A[j]);
            st[j] = fmaf(dA, st[j], du * sbc[t][nh * 8 + j]);
            ys = fmaf(st[j], sbc[t][16 + nh * 8 + j], ys);
        }
        ys += __shfl_xor_sync(0xffffffffu, ys, 1);
        if (nh == 0) {
            float g = sgt[t][p];
            float sg = g / (1.f + __expf(-g));
            g_yc[(size_t)(b * 60 + t) * 1536 + i] = (ys + hsv * Dv) * sg;
        }
    }
}

// ---------------- out-proj GEMM: g_h += g_yc(240,1536) @ out_w[l] -----------
// grid (6,15), 256 thr; tile 16x128, thread 2x4, cp.async double-buffered
__global__ void __launch_bounds__(256, 1) k_gemm_out(const float* __restrict__ out_w, int l) {
    __shared__ float As[2][16][32];
    __shared__ float Ws[2][32][128];
    const float* W = out_w + (size_t)l * 1536 * 768;
    int tid = threadIdx.x;
    int col0 = blockIdx.x * 128, row0 = blockIdx.y * 16;
    unsigned aA = su32(As), aW = su32(Ws);
    int arr = tid >> 3, af = (tid & 7) * 4;
    const float* asrc = &g_yc[(size_t)(row0 + arr) * 1536 + af];

#define ISSUE_OUT(s, k0) do { \
    if (tid < 128) CPA16(aA + (unsigned)(((s) * 512 + arr * 32 + af) * 4), asrc + (k0)); \
    _Pragma("unroll") \
    for (int p = 0; p < 4; p++) { int e = tid + p * 256; int kk = e >> 5, cc = (e & 31) * 4; \
        CPA16(aW + (unsigned)(((s) * 4096 + kk * 128 + cc) * 4), &W[(size_t)((k0) + kk) * 768 + col0 + cc]); } \
    CPCOMMIT(); } while (0)

    ISSUE_OUT(0, 0);
    int ty = tid >> 5, txx = tid & 31;
    float acc[8] = {0, 0, 0, 0, 0, 0, 0, 0};
#pragma unroll 1
    for (int kt = 0; kt < 48; kt++) {
        __syncthreads();
        if (kt < 47) ISSUE_OUT((kt + 1) & 1, (kt + 1) * 32); else CPCOMMIT();
        CPWAIT1();
        __syncthreads();
        int s = kt & 1;
#pragma unroll
        for (int kk = 0; kk < 32; kk++) {
            float a0 = As[s][ty][kk], a1 = As[s][ty + 8][kk];
            float4 b = *(const float4*)&Ws[s][kk][txx * 4];
            acc[0] = fmaf(a0, b.x, acc[0]); acc[1] = fmaf(a0, b.y, acc[1]);
            acc[2] = fmaf(a0, b.z, acc[2]); acc[3] = fmaf(a0, b.w, acc[3]);
            acc[4] = fmaf(a1, b.x, acc[4]); acc[5] = fmaf(a1, b.y, acc[5]);
            acc[6] = fmaf(a1, b.z, acc[6]); acc[7] = fmaf(a1, b.w, acc[7]);
        }
    }
    size_t o0 = (size_t)(row0 + ty) * 768 + col0 + txx * 4;
    float4 v0 = *(float4*)&g_h[o0];
    v0.x += acc[0]; v0.y += acc[1]; v0.z += acc[2]; v0.w += acc[3];
    *(float4*)&g_h[o0] = v0;
    float4 v1 = *(float4*)&g_h[o0 + 8 * 768];
    v1.x += acc[4]; v1.y += acc[5]; v1.z += acc[6]; v1.w += acc[7];
    *(float4*)&g_h[o0 + 8 * 768] = v1;
#undef ISSUE_OUT
}

// ---------------- final rmsnorm + attention logits --------------------------
__global__ void k_final(const float* __restrict__ fnorm_w,
                        const float* __restrict__ ws1, const float* __restrict__ ws2) {
    int r = blockIdx.x, tid = threadIdx.x;
    __shared__ float hf[768];
    __shared__ float al[128];
    __shared__ float red[256];
    float ss = 0.f;
    for (int k = tid; k < 768; k += 256) { float v = g_h[r * 768 + k]; ss += v * v; }
    red[tid] = ss;
    __syncthreads();
    for (int s = 128; s > 0; s >>= 1) { if (tid < s) red[tid] += red[tid + s]; __syncthreads(); }
    float rstd = rsqrtf(red[0] * (1.f / 768.f) + 1e-5f);
#pragma unroll
    for (int ii = 0; ii < 3; ii++) {
        int c = tid + ii * 256;
        float v = g_h[r * 768 + c] * rstd * fnorm_w[c];
        hf[c] = v;
        g_hf[r * 768 + c] = v;
    }
    __syncthreads();
    if (tid < 128) {
        float a = 0.f;
        for (int k = 0; k < 768; k++) a += hf[k] * ws1[k * 128 + tid];
        al[tid] = tanhf(a);
    }
    __syncthreads();
    if (tid < 4) {
        float s = 0.f;
        for (int d = 0; d < 128; d++) s += al[d] * ws2[d * 4 + tid];
        g_sc[r * 4 + tid] = s;
    }
}

// ---------------- softmax(axis=L) + pooling ---------------------------------
__global__ void k_pool() {
    int b = blockIdx.x >> 2, rr = blockIdx.x & 3;
    int tid = threadIdx.x;
    __shared__ float att[60];
    __shared__ float mx_s, inv_s;
    if (tid < 60) att[tid] = g_sc[(b * 60 + tid) * 4 + rr];
    __syncthreads();
    if (tid == 0) {
        float m = -1e30f;
        for (int t = 0; t < 60; t++) m = fmaxf(m, att[t]);
        mx_s = m;
    }
    __syncthreads();
    if (tid < 60) att[tid] = __expf(att[tid] - mx_s);
    __syncthreads();
    if (tid == 0) {
        float s = 0.f;
        for (int t = 0; t < 60; t++) s += att[t];
        inv_s = 1.f / s;
    }
    __syncthreads();
    for (int c = tid; c < 768; c += 256) {
        float acc = 0.f;
        for (int t = 0; t < 60; t++) acc += att[t] * g_hf[(b * 60 + t) * 768 + c];
        g_m[b * 3072 + rr * 768 + c] = acc * inv_s;
    }
}

// ---------------- output MLP ------------------------------------------------
__global__ void k_out_mlp(const float* __restrict__ ow1, const float* __restrict__ ob1,
                          const float* __restrict__ ow2, const float* __restrict__ ob2,
                          const float* __restrict__ ow3, const float* __restrict__ ob3,
                          float* __restrict__ out) {
    int b = blockIdx.x, tid = threadIdx.x;
    __shared__ float o1[256];
    __shared__ float o2[256];
    __shared__ float red[256];
    float a = ob1[tid];
    for (int k = 0; k < 3072; k++) a += g_m[b * 3072 + k] * ow1[k * 256 + tid];
    o1[tid] = fmaxf(a, 0.f);
    __syncthreads();
    a = ob2[tid];
    for (int k = 0; k < 256; k++) a += o1[k] * ow2[k * 256 + tid];
    o2[tid] = fmaxf(a, 0.f);
    __syncthreads();
    red[tid] = o2[tid] * ow3[tid];
    __syncthreads();
    for (int s = 128; s > 0; s >>= 1) { if (tid < s) red[tid] += red[tid + s]; __syncthreads(); }
    if (tid == 0) out[b] = red[0] + ob3[0];
}

// ---------------- launch ----------------------------------------------------
extern "C" void kernel_launch(void* const* d_in, const int* in_sizes, int n_in,
                              void* d_out, int out_size) {
    const float* x      = (const float*)d_in[0];
    const float* iw1    = (const float*)d_in[1];
    const float* ib1    = (const float*)d_in[2];
    const float* iw2    = (const float*)d_in[3];
    const float* ib2    = (const float*)d_in[4];
    const float* iw3    = (const float*)d_in[5];
    const float* ib3    = (const float*)d_in[6];
    const float* norm_w = (const float*)d_in[7];
    const float* in_w   = (const float*)d_in[8];
    const float* conv_w = (const float*)d_in[9];
    const float* conv_b = (const float*)d_in[10];
    const float* xp_w   = (const float*)d_in[11];
    const float* dt_w   = (const float*)d_in[12];
    const float* dt_b   = (const float*)d_in[13];
    const float* A_log  = (const float*)d_in[14];
    const float* Dp     = (const float*)d_in[15];
    const float* out_w  = (const float*)d_in[16];
    const float* fnorm_w= (const float*)d_in[17];
    const float* ws1    = (const float*)d_in[18];
    const float* ws2    = (const float*)d_in[19];
    const float* ow1    = (const float*)d_in[20];
    const float* ob1    = (const float*)d_in[21];
    const float* ow2    = (const float*)d_in[22];
    const float* ob2    = (const float*)d_in[23];
    const float* ow3    = (const float*)d_in[24];
    const float* ob3    = (const float*)d_in[25];

    k_in_mlp<<<BL, 256>>>(x, iw1, ib1, iw2, ib2, iw3, ib3);
    for (int l = 0; l < NLYR; l++) {
        k_norm<<<BL, 256>>>(norm_w, l);
        k_gemm_in<<<dim3(24, 15), 256>>>(in_w, l);
        k_sp<<<60, 256>>>(conv_w, conv_b, xp_w, l);
        k_dt<<<dim3(6, 30), 256>>>(dt_w, dt_b, l);
        k_scan<<<192, 64>>>(A_log, Dp, l);
        k_gemm_out<<<dim3(6, 15), 256>>>(out_w, l);
    }
    k_final<<<BL, 256>>>(fnorm_w, ws1, ws2);
    k_pool<<<16, 256>>>();
    k_out_mlp<<<4, 256>>>(ow1, ob1, ow2, ob2, ow3, ob3, (float*)d_out);
}